// round 1
// baseline (speedup 1.0000x reference)
#include <cuda_runtime.h>
#include <cuda_bf16.h>
#include <cstdint>

#define N_NODES  50000
#define N_EDGES  800000
#define N_GRAPHS 512
#define IN_C     128
#define HID      256
#define OUT_C    16

// ---------------- scratch (static device globals; no allocation) -------------
__device__ float g_agg[(size_t)N_NODES * HID];
__device__ float g_tmp[(size_t)N_NODES * HID];
__device__ float g_h  [(size_t)N_NODES * HID];
__device__ float g_pool[N_GRAPHS * HID];
__device__ float g_cnt [N_GRAPHS];
__device__ int   g_is64;

// ---------------- int32/int64 index-width autodetect -------------------------
// edge_index values are random in [0, 50000). If the array is int64 (LE),
// every odd 32-bit word is 0. If int32, those words are random indices; the
// chance the first 4 odd words are all zero is ~ (1/50000)^4 ~ 0.
__global__ void detect_kernel(const unsigned int* __restrict__ w) {
    g_is64 = ((w[1] | w[3] | w[5] | w[7]) == 0u) ? 1 : 0;
}

__device__ __forceinline__ int idx_at(const void* p, long long i) {
    if (g_is64) return (int)((const long long*)p)[i];
    return ((const int*)p)[i];
}

// ---------------- zero fill ---------------------------------------------------
__global__ void zero_kernel(float4* __restrict__ p, int n4) {
    int i = blockIdx.x * blockDim.x + threadIdx.x;
    if (i < n4) p[i] = make_float4(0.f, 0.f, 0.f, 0.f);
}

// ---------------- edge scatter-add (GIN aggregation) --------------------------
// one thread per (edge, float4-chunk); consecutive threads -> consecutive
// feature chunks (coalesced gather), float4 vector atomics on the scatter.
__global__ void edge_scatter(const float4* __restrict__ h4,
                             float4* __restrict__ agg4,
                             const void* __restrict__ ei,   // [2, N_EDGES]
                             int shift)                      // log2(C/4)
{
    long long idx = (long long)blockIdx.x * blockDim.x + threadIdx.x;
    long long total = (long long)N_EDGES << shift;
    if (idx >= total) return;
    int e = (int)(idx >> shift);
    int f = (int)(idx & ((1 << shift) - 1));
    int s = idx_at(ei, e);
    int d = idx_at(ei, (long long)N_EDGES + e);
    float4 v = h4[((size_t)s << shift) + f];
    atomicAdd(agg4 + ((size_t)d << shift) + f, v);
}

// ---------------- fused GEMM: C = act((A [+ A2]) @ W + bias) ------------------
// BM=BN=64, BK=16, 256 threads, 4x4 register tile, float4 smem traffic.
#define BM 64
#define BN 64
#define BKK 16

__global__ void gemm_bias_relu(const float* __restrict__ A,
                               const float* __restrict__ A2,   // may be null
                               const float* __restrict__ W,    // K x N row-major
                               const float* __restrict__ bias, // N
                               float* __restrict__ C,
                               int M, int K, int N, int doRelu)
{
    __shared__ float As[BKK][BM + 4];
    __shared__ float Bs[BKK][BN];

    int bm = blockIdx.x * BM;
    int bn = blockIdx.y * BN;
    int tid = threadIdx.x;          // 0..255
    int tx = tid & 15;              // col group
    int ty = tid >> 4;              // row group

    float acc[4][4] = {};

    for (int k0 = 0; k0 < K; k0 += BKK) {
        // load A tile (64 x 16), fused elementwise add; transpose into As[k][m]
        {
            int r  = tid >> 2;            // 0..63
            int kq = (tid & 3) * 4;       // 0,4,8,12
            int row = bm + r;
            float4 v = make_float4(0.f, 0.f, 0.f, 0.f);
            if (row < M) {
                v = *(const float4*)(A + (size_t)row * K + k0 + kq);
                if (A2) {
                    float4 u = *(const float4*)(A2 + (size_t)row * K + k0 + kq);
                    v.x += u.x; v.y += u.y; v.z += u.z; v.w += u.w;
                }
            }
            As[kq + 0][r] = v.x;
            As[kq + 1][r] = v.y;
            As[kq + 2][r] = v.z;
            As[kq + 3][r] = v.w;
        }
        // load B tile (16 x 64)
        {
            int kr = tid >> 4;            // 0..15
            int nq = (tid & 15) * 4;      // 0..60
            float4 v = *(const float4*)(W + (size_t)(k0 + kr) * N + bn + nq);
            *(float4*)&Bs[kr][nq] = v;
        }
        __syncthreads();

        #pragma unroll
        for (int k = 0; k < BKK; k++) {
            float4 a = *(const float4*)&As[k][ty * 4];
            float4 b = *(const float4*)&Bs[k][tx * 4];
            acc[0][0] += a.x * b.x; acc[0][1] += a.x * b.y; acc[0][2] += a.x * b.z; acc[0][3] += a.x * b.w;
            acc[1][0] += a.y * b.x; acc[1][1] += a.y * b.y; acc[1][2] += a.y * b.z; acc[1][3] += a.y * b.w;
            acc[2][0] += a.z * b.x; acc[2][1] += a.z * b.y; acc[2][2] += a.z * b.z; acc[2][3] += a.z * b.w;
            acc[3][0] += a.w * b.x; acc[3][1] += a.w * b.y; acc[3][2] += a.w * b.z; acc[3][3] += a.w * b.w;
        }
        __syncthreads();
    }

    float4 bv = *(const float4*)(bias + bn + tx * 4);
    #pragma unroll
    for (int i = 0; i < 4; i++) {
        int row = bm + ty * 4 + i;
        if (row < M) {
            float4 c;
            c.x = acc[i][0] + bv.x;
            c.y = acc[i][1] + bv.y;
            c.z = acc[i][2] + bv.z;
            c.w = acc[i][3] + bv.w;
            if (doRelu) {
                c.x = fmaxf(c.x, 0.f); c.y = fmaxf(c.y, 0.f);
                c.z = fmaxf(c.z, 0.f); c.w = fmaxf(c.w, 0.f);
            }
            *(float4*)(C + (size_t)row * N + bn + tx * 4) = c;
        }
    }
}

// ---------------- graph mean-pool scatter ------------------------------------
__global__ void pool_scatter(const float4* __restrict__ h4,
                             const void* __restrict__ batch,
                             float4* __restrict__ pool4,
                             float* __restrict__ cnt)
{
    int idx = blockIdx.x * blockDim.x + threadIdx.x;   // N_NODES * (HID/4)
    if (idx >= N_NODES * (HID / 4)) return;
    int node = idx >> 6;          // HID/4 == 64
    int f    = idx & 63;
    int g = idx_at(batch, node);
    atomicAdd(pool4 + (size_t)g * (HID / 4) + f, h4[(size_t)node * (HID / 4) + f]);
    if (f == 0) atomicAdd(&cnt[g], 1.0f);
}

// ---------------- final MLP: out = relu(pooled@W1+b1)@W2+b2 ------------------
__global__ void final_mlp(const float* __restrict__ sums,
                          const float* __restrict__ cnt,
                          const float* __restrict__ w1, const float* __restrict__ b1,
                          const float* __restrict__ w2, const float* __restrict__ b2,
                          float* __restrict__ out)
{
    __shared__ float p[HID];
    __shared__ float hh[HID];
    int g = blockIdx.x;
    int t = threadIdx.x;

    float c = fmaxf(cnt[g], 1.0f);
    p[t] = sums[(size_t)g * HID + t] / c;
    __syncthreads();

    float acc = b1[t];
    #pragma unroll 8
    for (int k = 0; k < HID; k++)
        acc += p[k] * w1[(size_t)k * HID + t];
    hh[t] = fmaxf(acc, 0.f);
    __syncthreads();

    int o  = t >> 4;    // 0..15 output channel
    int kk = t & 15;    // partial lane
    float s = 0.f;
    for (int k = kk; k < HID; k += 16)
        s += hh[k] * w2[(size_t)k * OUT_C + o];
    #pragma unroll
    for (int off = 8; off; off >>= 1)
        s += __shfl_xor_sync(0xffffffffu, s, off);
    if (kk == 0) out[(size_t)g * OUT_C + o] = s + b2[o];
}

// ---------------- launcher ----------------------------------------------------
extern "C" void kernel_launch(void* const* d_in, const int* in_sizes, int n_in,
                              void* d_out, int out_size)
{
    const float* x     = (const float*)d_in[0];
    const void*  ei    = d_in[1];
    const void*  batch = d_in[2];
    const float* w[16];
    for (int i = 0; i < 16; i++) w[i] = (const float*)d_in[3 + i];
    float* out = (float*)d_out;

    float *agg, *tmp, *h, *pool, *cnt;
    cudaGetSymbolAddress((void**)&agg,  g_agg);
    cudaGetSymbolAddress((void**)&tmp,  g_tmp);
    cudaGetSymbolAddress((void**)&h,    g_h);
    cudaGetSymbolAddress((void**)&pool, g_pool);
    cudaGetSymbolAddress((void**)&cnt,  g_cnt);

    detect_kernel<<<1, 1>>>((const unsigned int*)ei);

    for (int layer = 0; layer < 3; layer++) {
        const float* hin = (layer == 0) ? x : h;
        int K     = (layer == 0) ? IN_C : HID;
        int shift = (layer == 0) ? 5 : 6;           // log2(K/4)

        int zn4 = N_NODES * K / 4;
        zero_kernel<<<(zn4 + 255) / 256, 256>>>((float4*)agg, zn4);

        long long tot = (long long)N_EDGES << shift;
        edge_scatter<<<(unsigned)((tot + 255) / 256), 256>>>(
            (const float4*)hin, (float4*)agg, ei, shift);

        dim3 grid((N_NODES + BM - 1) / BM, HID / BN);
        gemm_bias_relu<<<grid, 256>>>(hin, agg, w[layer * 4 + 0], w[layer * 4 + 1],
                                      tmp, N_NODES, K, HID, 1);
        gemm_bias_relu<<<grid, 256>>>(tmp, nullptr, w[layer * 4 + 2], w[layer * 4 + 3],
                                      h, N_NODES, HID, HID, 1);
    }

    // pooling
    {
        int pn4 = N_GRAPHS * HID / 4;
        zero_kernel<<<(pn4 + 255) / 256, 256>>>((float4*)pool, pn4);
        zero_kernel<<<1, 256>>>((float4*)cnt, N_GRAPHS / 4);
        int tot = N_NODES * (HID / 4);
        pool_scatter<<<(tot + 255) / 256, 256>>>((const float4*)h, batch,
                                                 (float4*)pool, cnt);
    }

    final_mlp<<<N_GRAPHS, HID>>>(pool, cnt, w[12], w[13], w[14], w[15], out);
}

// round 2
// speedup vs baseline: 1.3005x; 1.3005x over previous
#include <cuda_runtime.h>
#include <cuda_bf16.h>
#include <cstdint>

#define N_NODES  50000
#define N_EDGES  800000
#define N_GRAPHS 512
#define IN_C     128
#define HID      256
#define OUT_C    16

// ---------------- scratch (static device globals; no allocation) -------------
__device__ float g_agg [(size_t)N_NODES * HID];
__device__ float g_tmp [(size_t)N_NODES * HID];
__device__ float g_h   [(size_t)N_NODES * HID];
__device__ float g_pool[N_GRAPHS * HID];
__device__ int   g_deg   [N_NODES];
__device__ int   g_ex    [N_NODES];
__device__ int   g_bsums [128];
__device__ int   g_rowptr[N_NODES + 1];
__device__ int   g_cursor[N_NODES];
__device__ int   g_csr   [N_EDGES];
__device__ int   g_gstart[N_GRAPHS + 1];
__device__ int   g_is64;

// ---------------- int32/int64 index-width autodetect -------------------------
__global__ void detect_kernel(const unsigned int* __restrict__ w) {
    g_is64 = ((w[1] | w[3] | w[5] | w[7]) == 0u) ? 1 : 0;
}
__device__ __forceinline__ int idx_at(const void* p, long long i) {
    if (g_is64) return (int)((const long long*)p)[i];
    return ((const int*)p)[i];
}

// ---------------- CSR build ----------------------------------------------------
__global__ void zero_int(int* __restrict__ p, int n) {
    int i = blockIdx.x * blockDim.x + threadIdx.x;
    if (i < n) p[i] = 0;
}

__global__ void deg_hist(const void* __restrict__ ei, int* __restrict__ deg) {
    int e = blockIdx.x * blockDim.x + threadIdx.x;
    if (e >= N_EDGES) return;
    int d = idx_at(ei, (long long)N_EDGES + e);
    atomicAdd(&deg[d], 1);
}

#define SCAN_B 512
__global__ void scan1(const int* __restrict__ deg, int* __restrict__ ex,
                      int* __restrict__ sums) {
    __shared__ int s[SCAN_B];
    int b = blockIdx.x, t = threadIdx.x;
    int i = b * SCAN_B + t;
    int v = (i < N_NODES) ? deg[i] : 0;
    s[t] = v; __syncthreads();
    for (int off = 1; off < SCAN_B; off <<= 1) {
        int x = (t >= off) ? s[t - off] : 0;
        __syncthreads();
        s[t] += x;
        __syncthreads();
    }
    if (i < N_NODES) ex[i] = s[t] - v;
    if (t == SCAN_B - 1) sums[b] = s[t];
}

__global__ void scan2(int* __restrict__ sums, int nb) {   // single block, 128 thr
    __shared__ int s[128];
    int t = threadIdx.x;
    int v = (t < nb) ? sums[t] : 0;
    s[t] = v; __syncthreads();
    for (int off = 1; off < 128; off <<= 1) {
        int x = (t >= off) ? s[t - off] : 0;
        __syncthreads();
        s[t] += x;
        __syncthreads();
    }
    if (t < nb) sums[t] = s[t] - v;   // exclusive
}

__global__ void scan3(const int* __restrict__ ex, const int* __restrict__ sums,
                      int* __restrict__ rowptr, int* __restrict__ cursor) {
    int i = blockIdx.x * blockDim.x + threadIdx.x;
    if (i < N_NODES) {
        int v = ex[i] + sums[i >> 9];
        rowptr[i] = v;
        cursor[i] = v;
    }
    if (i == 0) rowptr[N_NODES] = N_EDGES;
}

__global__ void csr_fill(const void* __restrict__ ei, int* __restrict__ cursor,
                         int* __restrict__ csr) {
    int e = blockIdx.x * blockDim.x + threadIdx.x;
    if (e >= N_EDGES) return;
    int s = idx_at(ei, e);
    int d = idx_at(ei, (long long)N_EDGES + e);
    int p = atomicAdd(&cursor[d], 1);
    csr[p] = s;
}

// ---------------- aggregation: out[i] = h[i] + sum_{j in N(i)} h[j] ----------
// one block per node, one thread per channel (blockDim == C); coalesced rows.
__global__ void aggregate(const float* __restrict__ h,
                          const int* __restrict__ rowptr,
                          const int* __restrict__ csr,
                          float* __restrict__ out, int C) {
    int node = blockIdx.x;
    int t = threadIdx.x;
    int beg = rowptr[node], end = rowptr[node + 1];
    float acc = h[(size_t)node * C + t];
    int e = beg;
    for (; e + 4 <= end; e += 4) {
        int s0 = csr[e], s1 = csr[e + 1], s2 = csr[e + 2], s3 = csr[e + 3];
        float v0 = h[(size_t)s0 * C + t];
        float v1 = h[(size_t)s1 * C + t];
        float v2 = h[(size_t)s2 * C + t];
        float v3 = h[(size_t)s3 * C + t];
        acc += v0; acc += v1; acc += v2; acc += v3;
    }
    for (; e < end; e++) acc += h[(size_t)csr[e] * C + t];
    out[(size_t)node * C + t] = acc;
}

// ---------------- GEMM: C = relu(A @ W + bias), 128x128 tile, 8x8 micro ------
#define TBM 128
#define TBN 128
#define TBK 16

__global__ __launch_bounds__(256, 2)
void gemm_bias_relu(const float* __restrict__ A,
                    const float* __restrict__ W,      // K x N row-major
                    const float* __restrict__ bias,   // N
                    float* __restrict__ C,
                    int M, int K, int N) {
    __shared__ float As[TBK][TBM + 4];
    __shared__ float Bs[TBK][TBN];

    int bm = blockIdx.x * TBM;
    int bn = blockIdx.y * TBN;
    int tid = threadIdx.x;
    int tx = tid & 15;
    int ty = tid >> 4;

    float acc[8][8] = {};

    for (int k0 = 0; k0 < K; k0 += TBK) {
        // A tile: 128 x 16 = 512 float4, 2 per thread; transpose into As[k][m]
        #pragma unroll
        for (int i = 0; i < 2; i++) {
            int li = tid + i * 256;       // 0..511
            int r  = li >> 2;             // 0..127
            int kq = (li & 3) * 4;        // 0,4,8,12
            int row = bm + r;
            float4 v = make_float4(0.f, 0.f, 0.f, 0.f);
            if (row < M) v = *(const float4*)(A + (size_t)row * K + k0 + kq);
            As[kq + 0][r] = v.x;
            As[kq + 1][r] = v.y;
            As[kq + 2][r] = v.z;
            As[kq + 3][r] = v.w;
        }
        // B tile: 16 x 128 = 512 float4, 2 per thread
        #pragma unroll
        for (int i = 0; i < 2; i++) {
            int li = tid + i * 256;
            int kr = li >> 5;             // 0..15
            int nq = (li & 31) * 4;       // 0..124
            *(float4*)&Bs[kr][nq] = *(const float4*)(W + (size_t)(k0 + kr) * N + bn + nq);
        }
        __syncthreads();

        #pragma unroll
        for (int k = 0; k < TBK; k++) {
            float a[8], b[8];
            *(float4*)&a[0] = *(const float4*)&As[k][ty * 4];
            *(float4*)&a[4] = *(const float4*)&As[k][64 + ty * 4];
            *(float4*)&b[0] = *(const float4*)&Bs[k][tx * 4];
            *(float4*)&b[4] = *(const float4*)&Bs[k][64 + tx * 4];
            #pragma unroll
            for (int i = 0; i < 8; i++)
                #pragma unroll
                for (int j = 0; j < 8; j++)
                    acc[i][j] += a[i] * b[j];
        }
        __syncthreads();
    }

    float bv[8];
    *(float4*)&bv[0] = *(const float4*)(bias + bn + tx * 4);
    *(float4*)&bv[4] = *(const float4*)(bias + bn + 64 + tx * 4);

    #pragma unroll
    for (int i = 0; i < 8; i++) {
        int row = bm + ((i < 4) ? (ty * 4 + i) : (64 + ty * 4 + i - 4));
        if (row >= M) continue;
        float4 c0, c1;
        c0.x = fmaxf(acc[i][0] + bv[0], 0.f);
        c0.y = fmaxf(acc[i][1] + bv[1], 0.f);
        c0.z = fmaxf(acc[i][2] + bv[2], 0.f);
        c0.w = fmaxf(acc[i][3] + bv[3], 0.f);
        c1.x = fmaxf(acc[i][4] + bv[4], 0.f);
        c1.y = fmaxf(acc[i][5] + bv[5], 0.f);
        c1.z = fmaxf(acc[i][6] + bv[6], 0.f);
        c1.w = fmaxf(acc[i][7] + bv[7], 0.f);
        *(float4*)(C + (size_t)row * N + bn + tx * 4)      = c0;
        *(float4*)(C + (size_t)row * N + bn + 64 + tx * 4) = c1;
    }
}

// ---------------- pooling over sorted batch -----------------------------------
__global__ void graph_bounds(const void* __restrict__ batch, int* __restrict__ gstart) {
    int g = blockIdx.x * blockDim.x + threadIdx.x;   // 0..N_GRAPHS inclusive
    if (g > N_GRAPHS) return;
    int lo = 0, hi = N_NODES;
    while (lo < hi) {
        int mid = (lo + hi) >> 1;
        if (idx_at(batch, mid) < g) lo = mid + 1; else hi = mid;
    }
    gstart[g] = lo;
}

__global__ void pool_mean(const float* __restrict__ h,
                          const int* __restrict__ gstart,
                          float* __restrict__ pooled) {
    int g = blockIdx.x;
    int t = threadIdx.x;           // HID threads
    int beg = gstart[g], end = gstart[g + 1];
    float acc = 0.f;
    for (int n = beg; n < end; n++)
        acc += h[(size_t)n * HID + t];
    float c = fmaxf((float)(end - beg), 1.0f);
    pooled[(size_t)g * HID + t] = acc / c;
}

// ---------------- final MLP: out = relu(pooled@W1+b1)@W2+b2 ------------------
__global__ void final_mlp(const float* __restrict__ pooled,
                          const float* __restrict__ w1, const float* __restrict__ b1,
                          const float* __restrict__ w2, const float* __restrict__ b2,
                          float* __restrict__ out) {
    __shared__ float p[HID];
    __shared__ float hh[HID];
    int g = blockIdx.x;
    int t = threadIdx.x;

    p[t] = pooled[(size_t)g * HID + t];
    __syncthreads();

    float acc = b1[t];
    #pragma unroll 8
    for (int k = 0; k < HID; k++)
        acc += p[k] * w1[(size_t)k * HID + t];
    hh[t] = fmaxf(acc, 0.f);
    __syncthreads();

    int o  = t >> 4;
    int kk = t & 15;
    float s = 0.f;
    for (int k = kk; k < HID; k += 16)
        s += hh[k] * w2[(size_t)k * OUT_C + o];
    #pragma unroll
    for (int off = 8; off; off >>= 1)
        s += __shfl_xor_sync(0xffffffffu, s, off);
    if (kk == 0) out[(size_t)g * OUT_C + o] = s + b2[o];
}

// ---------------- launcher ----------------------------------------------------
extern "C" void kernel_launch(void* const* d_in, const int* in_sizes, int n_in,
                              void* d_out, int out_size)
{
    const float* x     = (const float*)d_in[0];
    const void*  ei    = d_in[1];
    const void*  batch = d_in[2];
    const float* w[16];
    for (int i = 0; i < 16; i++) w[i] = (const float*)d_in[3 + i];
    float* out = (float*)d_out;

    float *agg, *tmp, *h, *pool;
    int *deg, *ex, *bsums, *rowptr, *cursor, *csr, *gstart;
    cudaGetSymbolAddress((void**)&agg,    g_agg);
    cudaGetSymbolAddress((void**)&tmp,    g_tmp);
    cudaGetSymbolAddress((void**)&h,      g_h);
    cudaGetSymbolAddress((void**)&pool,   g_pool);
    cudaGetSymbolAddress((void**)&deg,    g_deg);
    cudaGetSymbolAddress((void**)&ex,     g_ex);
    cudaGetSymbolAddress((void**)&bsums,  g_bsums);
    cudaGetSymbolAddress((void**)&rowptr, g_rowptr);
    cudaGetSymbolAddress((void**)&cursor, g_cursor);
    cudaGetSymbolAddress((void**)&csr,    g_csr);
    cudaGetSymbolAddress((void**)&gstart, g_gstart);

    detect_kernel<<<1, 1>>>((const unsigned int*)ei);

    // ---- CSR build (once, reused by all 3 layers) ----
    zero_int<<<(N_NODES + 255) / 256, 256>>>(deg, N_NODES);
    deg_hist<<<(N_EDGES + 255) / 256, 256>>>(ei, deg);
    int nb = (N_NODES + SCAN_B - 1) / SCAN_B;   // 98
    scan1<<<nb, SCAN_B>>>(deg, ex, bsums);
    scan2<<<1, 128>>>(bsums, nb);
    scan3<<<(N_NODES + 256) / 256, 256>>>(ex, bsums, rowptr, cursor);
    csr_fill<<<(N_EDGES + 255) / 256, 256>>>(ei, cursor, csr);

    // ---- 3 GIN layers ----
    for (int layer = 0; layer < 3; layer++) {
        const float* hin = (layer == 0) ? x : h;
        int K = (layer == 0) ? IN_C : HID;

        aggregate<<<N_NODES, K>>>(hin, rowptr, csr, agg, K);

        dim3 grid((N_NODES + TBM - 1) / TBM, HID / TBN);
        gemm_bias_relu<<<grid, 256>>>(agg, w[layer * 4 + 0], w[layer * 4 + 1],
                                      tmp, N_NODES, K, HID);
        gemm_bias_relu<<<grid, 256>>>(tmp, w[layer * 4 + 2], w[layer * 4 + 3],
                                      h, N_NODES, HID, HID);
    }

    // ---- pooling (batch is sorted) ----
    graph_bounds<<<3, 256>>>(batch, gstart);
    pool_mean<<<N_GRAPHS, HID>>>(h, gstart, pool);

    final_mlp<<<N_GRAPHS, HID>>>(pool, w[12], w[13], w[14], w[15], out);
}

// round 3
// speedup vs baseline: 2.7906x; 2.1458x over previous
#include <cuda_runtime.h>
#include <cuda_bf16.h>
#include <cstdint>

#define N_NODES  50000
#define N_EDGES  800000
#define N_GRAPHS 512
#define IN_C     128
#define HID      256
#define OUT_C    16

// ---------------- scratch (static device globals; no allocation) -------------
__device__ float g_agg [(size_t)N_NODES * HID];
__device__ float g_tmp [(size_t)N_NODES * HID];
__device__ float g_h   [(size_t)N_NODES * HID];
__device__ float g_pool[N_GRAPHS * HID];
__device__ int   g_deg   [N_NODES];
__device__ int   g_ex    [N_NODES];
__device__ int   g_bsums [128];
__device__ int   g_rowptr[N_NODES + 1];
__device__ int   g_cursor[N_NODES];
__device__ int   g_csr   [N_EDGES];
__device__ int   g_gstart[N_GRAPHS + 1];
__device__ int   g_is64;

// ---------------- int32/int64 index-width autodetect -------------------------
__global__ void detect_kernel(const unsigned int* __restrict__ w) {
    g_is64 = ((w[1] | w[3] | w[5] | w[7]) == 0u) ? 1 : 0;
}
__device__ __forceinline__ int idx_at(const void* p, long long i) {
    if (g_is64) return (int)((const long long*)p)[i];
    return ((const int*)p)[i];
}

// ---------------- CSR build ----------------------------------------------------
__global__ void zero_int(int* __restrict__ p, int n) {
    int i = blockIdx.x * blockDim.x + threadIdx.x;
    if (i < n) p[i] = 0;
}

__global__ void deg_hist(const void* __restrict__ ei, int* __restrict__ deg) {
    int e = blockIdx.x * blockDim.x + threadIdx.x;
    if (e >= N_EDGES) return;
    int d = idx_at(ei, (long long)N_EDGES + e);
    atomicAdd(&deg[d], 1);
}

#define SCAN_B 512
__global__ void scan1(const int* __restrict__ deg, int* __restrict__ ex,
                      int* __restrict__ sums) {
    __shared__ int s[SCAN_B];
    int b = blockIdx.x, t = threadIdx.x;
    int i = b * SCAN_B + t;
    int v = (i < N_NODES) ? deg[i] : 0;
    s[t] = v; __syncthreads();
    for (int off = 1; off < SCAN_B; off <<= 1) {
        int x = (t >= off) ? s[t - off] : 0;
        __syncthreads();
        s[t] += x;
        __syncthreads();
    }
    if (i < N_NODES) ex[i] = s[t] - v;
    if (t == SCAN_B - 1) sums[b] = s[t];
}

__global__ void scan2(int* __restrict__ sums, int nb) {   // single block, 128 thr
    __shared__ int s[128];
    int t = threadIdx.x;
    int v = (t < nb) ? sums[t] : 0;
    s[t] = v; __syncthreads();
    for (int off = 1; off < 128; off <<= 1) {
        int x = (t >= off) ? s[t - off] : 0;
        __syncthreads();
        s[t] += x;
        __syncthreads();
    }
    if (t < nb) sums[t] = s[t] - v;   // exclusive
}

__global__ void scan3(const int* __restrict__ ex, const int* __restrict__ sums,
                      int* __restrict__ rowptr, int* __restrict__ cursor) {
    int i = blockIdx.x * blockDim.x + threadIdx.x;
    if (i < N_NODES) {
        int v = ex[i] + sums[i >> 9];
        rowptr[i] = v;
        cursor[i] = v;
    }
    if (i == 0) rowptr[N_NODES] = N_EDGES;
}

__global__ void csr_fill(const void* __restrict__ ei, int* __restrict__ cursor,
                         int* __restrict__ csr) {
    int e = blockIdx.x * blockDim.x + threadIdx.x;
    if (e >= N_EDGES) return;
    int s = idx_at(ei, e);
    int d = idx_at(ei, (long long)N_EDGES + e);
    int p = atomicAdd(&cursor[d], 1);
    csr[p] = s;
}

// ---------------- aggregation: out[i] = h[i] + sum_{j in N(i)} h[j] ----------
// float4 lanes; C4 = C/4 threads per node, several nodes per 256-thread block.
__global__ void aggregate4(const float4* __restrict__ h4,
                           const int* __restrict__ rowptr,
                           const int* __restrict__ csr,
                           float4* __restrict__ out,
                           int c4shift)            // log2(C/4): 5 or 6
{
    int c4 = 1 << c4shift;
    int sub  = threadIdx.x >> c4shift;
    int t    = threadIdx.x & (c4 - 1);
    int npb  = 256 >> c4shift;
    int node = blockIdx.x * npb + sub;
    if (node >= N_NODES) return;

    int beg = rowptr[node], end = rowptr[node + 1];
    float4 acc = h4[((size_t)node << c4shift) + t];
    int e = beg;
    for (; e + 4 <= end; e += 4) {
        int s0 = csr[e], s1 = csr[e + 1], s2 = csr[e + 2], s3 = csr[e + 3];
        float4 v0 = h4[((size_t)s0 << c4shift) + t];
        float4 v1 = h4[((size_t)s1 << c4shift) + t];
        float4 v2 = h4[((size_t)s2 << c4shift) + t];
        float4 v3 = h4[((size_t)s3 << c4shift) + t];
        acc.x += v0.x + v1.x + v2.x + v3.x;
        acc.y += v0.y + v1.y + v2.y + v3.y;
        acc.z += v0.z + v1.z + v2.z + v3.z;
        acc.w += v0.w + v1.w + v2.w + v3.w;
    }
    for (; e < end; e++) {
        float4 v = h4[((size_t)csr[e] << c4shift) + t];
        acc.x += v.x; acc.y += v.y; acc.z += v.z; acc.w += v.w;
    }
    out[((size_t)node << c4shift) + t] = acc;
}

// ---------------- TF32 tensor-core GEMM: C = relu(A @ W + bias) ---------------
// BM=BN=128, BK=32, 256 threads (8 warps as 4x2), warp tile 32x64 via
// mma.sync.m16n8k8 tf32. Smem strides chosen conflict-free for fragment loads.
#define GBM 128
#define GBN 128
#define GBK 32
#define ASTRIDE 36     // 36 % 32 -> bank = 4*row + col, unique for 8x4 frag
#define BSTRIDE 136    // 136 % 32 -> bank = 8*row + col, unique for 4x8 frag

__device__ __forceinline__ uint32_t f2tf32(float f) {
    uint32_t r;
    asm("cvt.rna.tf32.f32 %0, %1;" : "=r"(r) : "f"(f));
    return r;
}

__global__ __launch_bounds__(256, 2)
void gemm_tf32(const float* __restrict__ A,
               const float* __restrict__ W,      // K x N row-major
               const float* __restrict__ bias,   // N
               float* __restrict__ C,
               int M, int K, int N)
{
    __shared__ uint32_t As[GBM][ASTRIDE];
    __shared__ uint32_t Bs[GBK][BSTRIDE];

    int bm = blockIdx.x * GBM;
    int bn = blockIdx.y * GBN;
    int tid  = threadIdx.x;
    int wid  = tid >> 5;
    int lane = tid & 31;
    int grp  = lane >> 2;     // 0..7
    int tig  = lane & 3;      // 0..3
    int wm = (wid & 3) * 32;  // warp row offset in tile
    int wn = (wid >> 2) * 64; // warp col offset in tile

    float acc[2][8][4];
    #pragma unroll
    for (int i = 0; i < 2; i++)
        #pragma unroll
        for (int j = 0; j < 8; j++)
            #pragma unroll
            for (int r = 0; r < 4; r++) acc[i][j][r] = 0.f;

    for (int k0 = 0; k0 < K; k0 += GBK) {
        // A tile: 128x32 floats -> tf32; 1024 float4, 4 per thread
        #pragma unroll
        for (int i = 0; i < 4; i++) {
            int li = tid + i * 256;
            int r  = li >> 3;          // 0..127
            int cq = (li & 7) * 4;     // 0..28
            float4 v = make_float4(0.f, 0.f, 0.f, 0.f);
            int row = bm + r;
            if (row < M) v = *(const float4*)(A + (size_t)row * K + k0 + cq);
            As[r][cq + 0] = f2tf32(v.x);
            As[r][cq + 1] = f2tf32(v.y);
            As[r][cq + 2] = f2tf32(v.z);
            As[r][cq + 3] = f2tf32(v.w);
        }
        // B tile: 32x128 floats -> tf32
        #pragma unroll
        for (int i = 0; i < 4; i++) {
            int li = tid + i * 256;
            int kr = li >> 5;          // 0..31
            int cq = (li & 31) * 4;    // 0..124
            float4 v = *(const float4*)(W + (size_t)(k0 + kr) * N + bn + cq);
            Bs[kr][cq + 0] = f2tf32(v.x);
            Bs[kr][cq + 1] = f2tf32(v.y);
            Bs[kr][cq + 2] = f2tf32(v.z);
            Bs[kr][cq + 3] = f2tf32(v.w);
        }
        __syncthreads();

        #pragma unroll
        for (int ks = 0; ks < GBK; ks += 8) {
            uint32_t af[2][4];
            #pragma unroll
            for (int mt = 0; mt < 2; mt++) {
                int r0 = wm + mt * 16 + grp;
                af[mt][0] = As[r0][ks + tig];
                af[mt][1] = As[r0 + 8][ks + tig];
                af[mt][2] = As[r0][ks + tig + 4];
                af[mt][3] = As[r0 + 8][ks + tig + 4];
            }
            uint32_t bf[8][2];
            #pragma unroll
            for (int nt = 0; nt < 8; nt++) {
                int c0 = wn + nt * 8 + grp;
                bf[nt][0] = Bs[ks + tig][c0];
                bf[nt][1] = Bs[ks + tig + 4][c0];
            }
            #pragma unroll
            for (int mt = 0; mt < 2; mt++)
                #pragma unroll
                for (int nt = 0; nt < 8; nt++) {
                    asm volatile(
                        "mma.sync.aligned.m16n8k8.row.col.f32.tf32.tf32.f32 "
                        "{%0,%1,%2,%3}, {%4,%5,%6,%7}, {%8,%9}, {%0,%1,%2,%3};"
                        : "+f"(acc[mt][nt][0]), "+f"(acc[mt][nt][1]),
                          "+f"(acc[mt][nt][2]), "+f"(acc[mt][nt][3])
                        : "r"(af[mt][0]), "r"(af[mt][1]),
                          "r"(af[mt][2]), "r"(af[mt][3]),
                          "r"(bf[nt][0]), "r"(bf[nt][1]));
                }
        }
        __syncthreads();
    }

    // epilogue: bias + relu, float2 stores
    #pragma unroll
    for (int mt = 0; mt < 2; mt++) {
        #pragma unroll
        for (int nt = 0; nt < 8; nt++) {
            int col = bn + wn + nt * 8 + 2 * tig;
            float b0 = bias[col], b1 = bias[col + 1];
            int r0 = bm + wm + mt * 16 + grp;
            if (r0 < M) {
                float2 c;
                c.x = fmaxf(acc[mt][nt][0] + b0, 0.f);
                c.y = fmaxf(acc[mt][nt][1] + b1, 0.f);
                *(float2*)(C + (size_t)r0 * N + col) = c;
            }
            if (r0 + 8 < M) {
                float2 c;
                c.x = fmaxf(acc[mt][nt][2] + b0, 0.f);
                c.y = fmaxf(acc[mt][nt][3] + b1, 0.f);
                *(float2*)(C + (size_t)(r0 + 8) * N + col) = c;
            }
        }
    }
}

// ---------------- pooling over sorted batch -----------------------------------
__global__ void graph_bounds(const void* __restrict__ batch, int* __restrict__ gstart) {
    int g = blockIdx.x * blockDim.x + threadIdx.x;
    if (g > N_GRAPHS) return;
    int lo = 0, hi = N_NODES;
    while (lo < hi) {
        int mid = (lo + hi) >> 1;
        if (idx_at(batch, mid) < g) lo = mid + 1; else hi = mid;
    }
    gstart[g] = lo;
}

__global__ void pool_mean(const float* __restrict__ h,
                          const int* __restrict__ gstart,
                          float* __restrict__ pooled) {
    int g = blockIdx.x;
    int t = threadIdx.x;           // HID threads
    int beg = gstart[g], end = gstart[g + 1];
    float acc = 0.f;
    for (int n = beg; n < end; n++)
        acc += h[(size_t)n * HID + t];
    float c = fmaxf((float)(end - beg), 1.0f);
    pooled[(size_t)g * HID + t] = acc / c;
}

// ---------------- final MLP: out = relu(pooled@W1+b1)@W2+b2 ------------------
__global__ void final_mlp(const float* __restrict__ pooled,
                          const float* __restrict__ w1, const float* __restrict__ b1,
                          const float* __restrict__ w2, const float* __restrict__ b2,
                          float* __restrict__ out) {
    __shared__ float p[HID];
    __shared__ float hh[HID];
    int g = blockIdx.x;
    int t = threadIdx.x;

    p[t] = pooled[(size_t)g * HID + t];
    __syncthreads();

    float acc = b1[t];
    #pragma unroll 8
    for (int k = 0; k < HID; k++)
        acc += p[k] * w1[(size_t)k * HID + t];
    hh[t] = fmaxf(acc, 0.f);
    __syncthreads();

    int o  = t >> 4;
    int kk = t & 15;
    float s = 0.f;
    for (int k = kk; k < HID; k += 16)
        s += hh[k] * w2[(size_t)k * OUT_C + o];
    #pragma unroll
    for (int off = 8; off; off >>= 1)
        s += __shfl_xor_sync(0xffffffffu, s, off);
    if (kk == 0) out[(size_t)g * OUT_C + o] = s + b2[o];
}

// ---------------- launcher ----------------------------------------------------
extern "C" void kernel_launch(void* const* d_in, const int* in_sizes, int n_in,
                              void* d_out, int out_size)
{
    const float* x     = (const float*)d_in[0];
    const void*  ei    = d_in[1];
    const void*  batch = d_in[2];
    const float* w[16];
    for (int i = 0; i < 16; i++) w[i] = (const float*)d_in[3 + i];
    float* out = (float*)d_out;

    float *agg, *tmp, *h, *pool;
    int *deg, *ex, *bsums, *rowptr, *cursor, *csr, *gstart;
    cudaGetSymbolAddress((void**)&agg,    g_agg);
    cudaGetSymbolAddress((void**)&tmp,    g_tmp);
    cudaGetSymbolAddress((void**)&h,      g_h);
    cudaGetSymbolAddress((void**)&pool,   g_pool);
    cudaGetSymbolAddress((void**)&deg,    g_deg);
    cudaGetSymbolAddress((void**)&ex,     g_ex);
    cudaGetSymbolAddress((void**)&bsums,  g_bsums);
    cudaGetSymbolAddress((void**)&rowptr, g_rowptr);
    cudaGetSymbolAddress((void**)&cursor, g_cursor);
    cudaGetSymbolAddress((void**)&csr,    g_csr);
    cudaGetSymbolAddress((void**)&gstart, g_gstart);

    detect_kernel<<<1, 1>>>((const unsigned int*)ei);

    // ---- CSR build (once, reused by all 3 layers) ----
    zero_int<<<(N_NODES + 255) / 256, 256>>>(deg, N_NODES);
    deg_hist<<<(N_EDGES + 255) / 256, 256>>>(ei, deg);
    int nb = (N_NODES + SCAN_B - 1) / SCAN_B;   // 98
    scan1<<<nb, SCAN_B>>>(deg, ex, bsums);
    scan2<<<1, 128>>>(bsums, nb);
    scan3<<<(N_NODES + 256) / 256, 256>>>(ex, bsums, rowptr, cursor);
    csr_fill<<<(N_EDGES + 255) / 256, 256>>>(ei, cursor, csr);

    // ---- 3 GIN layers ----
    for (int layer = 0; layer < 3; layer++) {
        const float* hin = (layer == 0) ? x : h;
        int K = (layer == 0) ? IN_C : HID;
        int c4shift = (layer == 0) ? 5 : 6;
        int npb = 256 >> c4shift;

        aggregate4<<<(N_NODES + npb - 1) / npb, 256>>>(
            (const float4*)hin, rowptr, csr, (float4*)agg, c4shift);

        dim3 grid((N_NODES + GBM - 1) / GBM, HID / GBN);
        gemm_tf32<<<grid, 256>>>(agg, w[layer * 4 + 0], w[layer * 4 + 1],
                                 tmp, N_NODES, K, HID);
        gemm_tf32<<<grid, 256>>>(tmp, w[layer * 4 + 2], w[layer * 4 + 3],
                                 h, N_NODES, HID, HID);
    }

    // ---- pooling (batch is sorted) ----
    graph_bounds<<<3, 256>>>(batch, gstart);
    pool_mean<<<N_GRAPHS, HID>>>(h, gstart, pool);

    final_mlp<<<N_GRAPHS, HID>>>(pool, w[12], w[13], w[14], w[15], out);
}